// round 5
// baseline (speedup 1.0000x reference)
#include <cuda_runtime.h>

// Problem constants
#define B_  4096
#define C_  32000
#define D_  128
#define K2  256          // combined GEMM K = 2*D
#define ALPHA 0.1f

// ---------------- device scratch (no allocations allowed) ----------------
__device__ float g_A [(size_t)B_ * K2];     //   4 MB   [f^2 | f]
__device__ float g_Bm[(size_t)C_ * K2];     //  32 MB   [inv | -2*mu*inv]
__device__ float g_cc  [C_];                // sum mu^2*inv per class
__device__ float g_slog[C_];                // sum log_covs per class
__device__ float g_dist[(size_t)B_ * C_];   // 524 MB   dist matrix
__device__ float g_lse1[B_];
__device__ float g_lse2[B_];
__device__ int   g_label[B_];
__device__ int   g_is64;
__device__ float g_pcd [64];
__device__ float g_pdet[64];

// ---------------- f32x2 packed helpers (sm_10x: full-rate fp32 needs FFMA2) ----
__device__ __forceinline__ unsigned long long pack2(float x) {
    unsigned long long r;
    asm("mov.b64 %0, {%1, %1};" : "=l"(r) : "f"(x));
    return r;
}
__device__ __forceinline__ void fma2(unsigned long long& d,
                                     unsigned long long a,
                                     unsigned long long b) {
    asm("fma.rn.f32x2 %0, %1, %2, %0;" : "+l"(d) : "l"(a), "l"(b));
}

// ---------------- label dtype detection (int32 vs int64) ----------------
// If the buffer is int64 (LE), every odd 32-bit word in the first 4096 ints is a
// zero hi-word (labels < 32000). If it is int32, those words are random labels.
__global__ void k_detect(const int* __restrict__ lab32) {
    __shared__ int any;
    if (threadIdx.x == 0) any = 0;
    __syncthreads();
    int acc = 0;
    for (int i = 1 + 2 * threadIdx.x; i < 4096; i += 2 * blockDim.x)
        acc |= lab32[i];
    if (acc) atomicOr(&any, 1);
    __syncthreads();
    if (threadIdx.x == 0) g_is64 = (any == 0) ? 1 : 0;
}

__global__ void k_gather(const int* __restrict__ lab32) {
    int b = blockIdx.x * blockDim.x + threadIdx.x;
    if (b < B_) {
        int idx = g_is64 ? 2 * b : b;   // single guarded load, never OOB
        g_label[b] = lab32[idx];
    }
}

// ---------------- prep A: [f^2 | f] ----------------
__global__ void k_prepA(const float* __restrict__ feat) {
    int i = blockIdx.x * blockDim.x + threadIdx.x;
    if (i < B_ * D_) {
        int b = i >> 7, d = i & 127;
        float f = feat[i];
        g_A[(size_t)b * K2 + d]      = f * f;
        g_A[(size_t)b * K2 + D_ + d] = f;
    }
}

// ---------------- prep B: [inv | -2*mu*inv], cc, slog ----------------
__global__ void k_prepB(const float* __restrict__ centers,
                        const float* __restrict__ log_covs) {
    int c = blockIdx.x;
    int d = threadIdx.x;   // 128 threads
    float lc  = log_covs[(size_t)c * D_ + d];
    float inv = expf(-lc);
    float mu  = centers[(size_t)c * D_ + d];
    g_Bm[(size_t)c * K2 + d]      = inv;
    g_Bm[(size_t)c * K2 + D_ + d] = -2.0f * mu * inv;

    __shared__ float s1[128], s2[128];
    s1[d] = mu * mu * inv;
    s2[d] = lc;
    __syncthreads();
    for (int off = 64; off > 0; off >>= 1) {
        if (d < off) { s1[d] += s1[d + off]; s2[d] += s2[d + off]; }
        __syncthreads();
    }
    if (d == 0) { g_cc[c] = s1[0]; g_slog[c] = s2[0]; }
}

// ---------------- GEMM: dist = A @ Bm^T + cc ----------------
// 128x128 block tile, BK=16, double-buffered smem, 8x8 thread tile,
// f32x2 packed FMAs (column-paired accumulators).
__global__ void __launch_bounds__(256) k_gemm() {
    __shared__ float As[2][16][132];
    __shared__ float Bs[2][16][132];

    const int tid = threadIdx.x;
    const int bm = blockIdx.y * 128;
    const int bn = blockIdx.x * 128;
    const int tx = tid & 15, ty = tid >> 4;
    const int lrow = tid >> 2;          // 0..63 (+64)
    const int lkq  = (tid & 3) << 2;    // 0,4,8,12

    unsigned long long acc[8][4];
#pragma unroll
    for (int i = 0; i < 8; i++)
#pragma unroll
        for (int j = 0; j < 4; j++) acc[i][j] = 0ull;

    float4 ra[2], rb[2];
    auto fetch = [&](int s) {
        int k0 = s * 16 + lkq;
#pragma unroll
        for (int r = 0; r < 2; r++) {
            int row = lrow + r * 64;
            ra[r] = *(const float4*)(g_A  + (size_t)(bm + row) * K2 + k0);
            rb[r] = *(const float4*)(g_Bm + (size_t)(bn + row) * K2 + k0);
        }
    };
    auto stash = [&](int buf) {
#pragma unroll
        for (int r = 0; r < 2; r++) {
            int row = lrow + r * 64;
            As[buf][lkq + 0][row] = ra[r].x;  As[buf][lkq + 1][row] = ra[r].y;
            As[buf][lkq + 2][row] = ra[r].z;  As[buf][lkq + 3][row] = ra[r].w;
            Bs[buf][lkq + 0][row] = rb[r].x;  Bs[buf][lkq + 1][row] = rb[r].y;
            Bs[buf][lkq + 2][row] = rb[r].z;  Bs[buf][lkq + 3][row] = rb[r].w;
        }
    };

    fetch(0); stash(0);
    __syncthreads();

#pragma unroll 1
    for (int s = 0; s < 16; s++) {
        int buf = s & 1;
        if (s < 15) fetch(s + 1);
#pragma unroll
        for (int kk = 0; kk < 16; kk++) {
            float4 a0 = *(const float4*)&As[buf][kk][ty * 8];
            float4 a1 = *(const float4*)&As[buf][kk][ty * 8 + 4];
            float4 b0 = *(const float4*)&Bs[buf][kk][tx * 8];
            float4 b1 = *(const float4*)&Bs[buf][kk][tx * 8 + 4];
            unsigned long long pb[4];
            pb[0] = ((const unsigned long long*)&b0)[0];
            pb[1] = ((const unsigned long long*)&b0)[1];
            pb[2] = ((const unsigned long long*)&b1)[0];
            pb[3] = ((const unsigned long long*)&b1)[1];
            float av[8] = {a0.x, a0.y, a0.z, a0.w, a1.x, a1.y, a1.z, a1.w};
#pragma unroll
            for (int i = 0; i < 8; i++) {
                unsigned long long pa = pack2(av[i]);
#pragma unroll
                for (int j = 0; j < 4; j++) fma2(acc[i][j], pa, pb[j]);
            }
        }
        if (s < 15) stash(buf ^ 1);
        __syncthreads();
    }

    // epilogue: dist = acc + cc[col]
    float ccv[8];
#pragma unroll
    for (int j = 0; j < 8; j++) ccv[j] = g_cc[bn + tx * 8 + j];
#pragma unroll
    for (int i = 0; i < 8; i++) {
        int m = bm + ty * 8 + i;
        float o[8];
#pragma unroll
        for (int j = 0; j < 4; j++) {
            float2 v = *(float2*)&acc[i][j];
            o[2 * j]     = v.x + ccv[2 * j];
            o[2 * j + 1] = v.y + ccv[2 * j + 1];
        }
        size_t base = (size_t)m * C_ + bn + tx * 8;
        *(float4*)(g_dist + base)     = make_float4(o[0], o[1], o[2], o[3]);
        *(float4*)(g_dist + base + 4) = make_float4(o[4], o[5], o[6], o[7]);
    }
}

// ---------------- per-row dual online logsumexp ----------------
__global__ void __launch_bounds__(256) k_rowreduce() {
    int b = blockIdx.x;
    int tid = threadIdx.x;
    int lab = g_label[b];
    const float4* r4  = (const float4*)(g_dist + (size_t)b * C_);
    const float4* sl4 = (const float4*)g_slog;

    float m1 = -1e30f, s1 = 0.f, m2 = -1e30f, s2 = 0.f;
    for (int c4 = tid; c4 < C_ / 4; c4 += 256) {
        float4 dv = r4[c4];
        float4 sv = sl4[c4];
        float dd[4] = {dv.x, dv.y, dv.z, dv.w};
        float ss[4] = {sv.x, sv.y, sv.z, sv.w};
        int cbase = c4 * 4;
#pragma unroll
        for (int j = 0; j < 4; j++) {
            float x = -0.5f * (ss[j] + dd[j]);
            if (x > m1) { s1 = s1 * __expf(m1 - x) + 1.f; m1 = x; }
            else        { s1 += __expf(x - m1); }
            float x2 = (cbase + j == lab) ? -0.5f * (ss[j] + (1.f + ALPHA) * dd[j]) : x;
            if (x2 > m2) { s2 = s2 * __expf(m2 - x2) + 1.f; m2 = x2; }
            else         { s2 += __expf(x2 - m2); }
        }
    }

    __shared__ float shm[256], shs[256];
    // variant 1
    shm[tid] = m1; shs[tid] = s1; __syncthreads();
    for (int off = 128; off > 0; off >>= 1) {
        if (tid < off) {
            float ma = shm[tid], sa = shs[tid];
            float mb = shm[tid + off], sb = shs[tid + off];
            float M = fmaxf(ma, mb);
            shm[tid] = M;
            shs[tid] = sa * __expf(ma - M) + sb * __expf(mb - M);
        }
        __syncthreads();
    }
    if (tid == 0) g_lse1[b] = shm[0] + logf(shs[0]);
    __syncthreads();
    // variant 2 (margin)
    shm[tid] = m2; shs[tid] = s2; __syncthreads();
    for (int off = 128; off > 0; off >>= 1) {
        if (tid < off) {
            float ma = shm[tid], sa = shs[tid];
            float mb = shm[tid + off], sb = shs[tid + off];
            float M = fmaxf(ma, mb);
            shm[tid] = M;
            shs[tid] = sa * __expf(ma - M) + sb * __expf(mb - M);
        }
        __syncthreads();
    }
    if (tid == 0) g_lse2[b] = shm[0] + logf(shs[0]);
}

// ---------------- final write: logits + margin_logits ----------------
__global__ void k_final(float* __restrict__ out) {
    size_t i4 = (size_t)blockIdx.x * blockDim.x + threadIdx.x;
    const size_t total4 = (size_t)B_ * C_ / 4;
    if (i4 >= total4) return;
    int b  = (int)(i4 / (C_ / 4));
    int c4 = (int)(i4 % (C_ / 4));
    int c  = c4 * 4;

    float4 dv = ((const float4*)g_dist)[i4];
    float4 sv = ((const float4*)g_slog)[c4];
    int lab = g_label[b];
    float l1 = g_lse1[b], l2 = g_lse2[b];

    float dd[4] = {dv.x, dv.y, dv.z, dv.w};
    float ss[4] = {sv.x, sv.y, sv.z, sv.w};
    float r1[4], r2[4];
#pragma unroll
    for (int j = 0; j < 4; j++) {
        float x = -0.5f * (ss[j] + dd[j]);
        r1[j] = x - l1;
        float x2 = (c + j == lab) ? -0.5f * (ss[j] + (1.f + ALPHA) * dd[j]) : x;
        r2[j] = x2 - l2;
    }
    ((float4*)out)[i4] = make_float4(r1[0], r1[1], r1[2], r1[3]);
    ((float4*)(out + (size_t)B_ * C_))[i4] = make_float4(r2[0], r2[1], r2[2], r2[3]);
}

// ---------------- scalars: cdist, reg, likelihood ----------------
__global__ void __launch_bounds__(256) k_scal1(const float* __restrict__ feat,
                                               const float* __restrict__ centers) {
    int tid = threadIdx.x, blk = blockIdx.x;  // 64 blocks
    float cd = 0.f, det = 0.f;
    for (int i = blk * 256 + tid; i < B_ * D_; i += 64 * 256) {
        int b = i >> 7, d = i & 127;
        int lab = g_label[b];
        float diff = feat[i] - centers[(size_t)lab * D_ + d];
        cd += diff * diff;
        if (d == 0) det += g_slog[lab];
    }
    __shared__ float s1[256], s2[256];
    s1[tid] = cd; s2[tid] = det; __syncthreads();
    for (int off = 128; off > 0; off >>= 1) {
        if (tid < off) { s1[tid] += s1[tid + off]; s2[tid] += s2[tid + off]; }
        __syncthreads();
    }
    if (tid == 0) { g_pcd[blk] = s1[0]; g_pdet[blk] = s2[0]; }
}

__global__ void k_scal2(float* __restrict__ out) {
    if (threadIdx.x == 0 && blockIdx.x == 0) {
        float cd = 0.f, det = 0.f;
        for (int i = 0; i < 64; i++) { cd += g_pcd[i]; det += g_pdet[i]; }
        float cdist = cd * 0.5f;
        float reg   = 0.5f * (det + 1e-8f);
        float like  = (cdist - reg) / (float)B_;
        size_t off = (size_t)2 * B_ * C_;
        out[off + 0] = like;
        out[off + 1] = cdist;
        out[off + 2] = reg;
    }
}

// ---------------- launch ----------------
extern "C" void kernel_launch(void* const* d_in, const int* in_sizes, int n_in,
                              void* d_out, int out_size) {
    const float* feat     = (const float*)d_in[0];
    const int*   lab      = (const int*)  d_in[1];
    const float* centers  = (const float*)d_in[2];
    const float* log_covs = (const float*)d_in[3];
    float* out = (float*)d_out;

    k_detect<<<1, 256>>>(lab);
    k_gather<<<16, 256>>>(lab);
    k_prepA<<<(B_ * D_ + 255) / 256, 256>>>(feat);
    k_prepB<<<C_, 128>>>(centers, log_covs);

    dim3 grid(C_ / 128, B_ / 128);   // 250 x 32
    k_gemm<<<grid, 256>>>();

    k_rowreduce<<<B_, 256>>>();
    k_final<<<(int)(((size_t)B_ * C_ / 4 + 255) / 256), 256>>>(out);

    k_scal1<<<64, 256>>>(feat, centers);
    k_scal2<<<1, 32>>>(out);
}

// round 10
// speedup vs baseline: 3.3331x; 3.3331x over previous
#include <cuda_runtime.h>
#include <cuda_bf16.h>
#include <cstdint>

#define B_  4096
#define C_  32000
#define D_  128
#define K3  768          // 3 regions * 256 (split-precision GEMM)
#define ALPHA 0.1f

// ---------------- device scratch ----------------
__device__ __nv_bfloat16 g_A2[(size_t)B_ * K3];   //  6.3 MB  [Ahi | Ahi | Alo]
__device__ __nv_bfloat16 g_B2[(size_t)C_ * K3];   // 49.2 MB  [Bhi | Blo | Bhi]
__device__ float g_cc  [C_];
__device__ float g_slog[C_];
__device__ float g_dist[(size_t)B_ * C_];         // 524 MB
__device__ float g_lse1[B_];
__device__ float g_lse2[B_];
__device__ int   g_label[B_];
__device__ int   g_is64;
__device__ float g_pcd [64];
__device__ float g_pdet[64];

// ================= helpers =================
__device__ __forceinline__ uint32_t smem_to_u32(const void* smem_ptr) {
    uint32_t addr;
    asm("{ .reg .u64 tmp; cvta.to.shared.u64 tmp, %1; cvt.u32.u64 %0, tmp; }"
        : "=r"(addr) : "l"(smem_ptr));
    return addr;
}
__device__ __forceinline__ void cp_async16(uint32_t dst, const void* src) {
    asm volatile("cp.async.cg.shared.global [%0], [%1], 16;"
                 :: "r"(dst), "l"(src) : "memory");
}
__device__ __forceinline__ void cp_commit() {
    asm volatile("cp.async.commit_group;" ::: "memory");
}
template<int N>
__device__ __forceinline__ void cp_wait() {
    asm volatile("cp.async.wait_group %0;" :: "n"(N) : "memory");
}
__device__ __forceinline__ void ldmatrix_x4(uint32_t* r, uint32_t addr) {
    asm volatile("ldmatrix.sync.aligned.m8n8.x4.shared.b16 {%0,%1,%2,%3}, [%4];"
                 : "=r"(r[0]), "=r"(r[1]), "=r"(r[2]), "=r"(r[3]) : "r"(addr));
}
__device__ __forceinline__ void mma_bf16(float* d, const uint32_t* a,
                                         uint32_t b0, uint32_t b1) {
    asm volatile(
        "mma.sync.aligned.m16n8k16.row.col.f32.bf16.bf16.f32 "
        "{%0,%1,%2,%3}, {%4,%5,%6,%7}, {%8,%9}, {%0,%1,%2,%3};"
        : "+f"(d[0]), "+f"(d[1]), "+f"(d[2]), "+f"(d[3])
        : "r"(a[0]), "r"(a[1]), "r"(a[2]), "r"(a[3]), "r"(b0), "r"(b1));
}

// ================= label dtype detect / gather =================
__global__ void k_detect(const int* __restrict__ lab32) {
    __shared__ int any;
    if (threadIdx.x == 0) any = 0;
    __syncthreads();
    int acc = 0;
    for (int i = 1 + 2 * threadIdx.x; i < 4096; i += 2 * blockDim.x)
        acc |= lab32[i];
    if (acc) atomicOr(&any, 1);
    __syncthreads();
    if (threadIdx.x == 0) g_is64 = (any == 0) ? 1 : 0;
}
__global__ void k_gather(const int* __restrict__ lab32) {
    int b = blockIdx.x * blockDim.x + threadIdx.x;
    if (b < B_) g_label[b] = lab32[g_is64 ? 2 * b : b];
}

// ================= split-precision prep =================
__device__ __forceinline__ void split_bf16(float v, __nv_bfloat16& hi, __nv_bfloat16& lo) {
    hi = __float2bfloat16(v);
    lo = __float2bfloat16(v - __bfloat162float(hi));
}

// A' row (768): [f2hi(128) | fhi(128) | f2hi | fhi | f2lo | flo]
__global__ void k_prepA(const float* __restrict__ feat) {
    int i = blockIdx.x * blockDim.x + threadIdx.x;
    if (i >= B_ * D_) return;
    int b = i >> 7, d = i & 127;
    float f = feat[i];
    __nv_bfloat16 h0, l0, h1, l1;
    split_bf16(f * f, h0, l0);
    split_bf16(f,     h1, l1);
    size_t rb = (size_t)b * K3;
    g_A2[rb +   0 + d] = h0;  g_A2[rb + 128 + d] = h1;
    g_A2[rb + 256 + d] = h0;  g_A2[rb + 384 + d] = h1;
    g_A2[rb + 512 + d] = l0;  g_A2[rb + 640 + d] = l1;
}

// B' row (768): [invhi | w1hi | invlo | w1lo | invhi | w1hi], w1 = -2*mu*inv
__global__ void k_prepB(const float* __restrict__ centers,
                        const float* __restrict__ log_covs) {
    int c = blockIdx.x;
    int d = threadIdx.x;   // 128
    float lc  = log_covs[(size_t)c * D_ + d];
    float inv = expf(-lc);
    float mu  = centers[(size_t)c * D_ + d];
    float w1  = -2.0f * mu * inv;
    __nv_bfloat16 h0, l0, h1, l1;
    split_bf16(inv, h0, l0);
    split_bf16(w1,  h1, l1);
    size_t rb = (size_t)c * K3;
    g_B2[rb +   0 + d] = h0;  g_B2[rb + 128 + d] = h1;
    g_B2[rb + 256 + d] = l0;  g_B2[rb + 384 + d] = l1;
    g_B2[rb + 512 + d] = h0;  g_B2[rb + 640 + d] = h1;

    __shared__ float s1[128], s2[128];
    s1[d] = mu * mu * inv;
    s2[d] = lc;
    __syncthreads();
    for (int off = 64; off > 0; off >>= 1) {
        if (d < off) { s1[d] += s1[d + off]; s2[d] += s2[d + off]; }
        __syncthreads();
    }
    if (d == 0) { g_cc[c] = s1[0]; g_slog[c] = s2[0]; }
}

// ================= mma.sync GEMM: dist = A' @ B'^T + cc =================
// CTA tile 128x128, K-chunk 64, double-buffered cp.async smem, 8 warps of 64x32.
#define KC      64
#define NCHUNK  12
#define TILE_B  16384              // 128 rows x 128 bytes
#define BUF_B   (2 * TILE_B)       // A + B tiles per buffer

__global__ void __launch_bounds__(256, 2) k_gemm_mma() {
    extern __shared__ char dsm[];
    const uint32_t tiles = smem_to_u32(dsm);
    __shared__ float s_cc[128];

    const int tid = threadIdx.x;
    const int wid = tid >> 5, l = tid & 31;
    const int warp_m = wid >> 2;         // 0..1
    const int warp_n = wid & 3;          // 0..3
    const int bn = blockIdx.x * 128;
    const int bm = blockIdx.y * 128;

    if (tid < 128) s_cc[tid] = g_cc[bn + tid];

    const __nv_bfloat16* gA = g_A2 + (size_t)bm * K3;
    const __nv_bfloat16* gB = g_B2 + (size_t)bn * K3;

    // cp.async: thread t covers 16B units u = tid + j*256 (1024 units / tile)
    auto load_chunk = [&](int c, int buf) {
        uint32_t dstA = tiles + buf * BUF_B;
        uint32_t dstB = dstA + TILE_B;
        const __nv_bfloat16* gAc = gA + c * KC;
        const __nv_bfloat16* gBc = gB + c * KC;
#pragma unroll
        for (int j = 0; j < 4; j++) {
            int u = tid + j * 256;
            int r = u >> 3, q = u & 7;
            uint32_t off = (uint32_t)(r * 128 + ((q ^ (r & 7)) << 4));
            cp_async16(dstA + off, gAc + (size_t)r * K3 + q * 8);
            cp_async16(dstB + off, gBc + (size_t)r * K3 + q * 8);
        }
        cp_commit();
    };

    // ldmatrix lane geometry
    const int xorv = l & 7;
    const int arow = warp_m * 64 + ((l >> 3) & 1) * 8 + (l & 7);  // + mt*16
    const int akh  = (l >> 4) & 1;
    const int brow = warp_n * 32 + ((l >> 4) & 1) * 8 + (l & 7);  // + p*16
    const int bkh  = (l >> 3) & 1;

    float acc[4][4][4];
#pragma unroll
    for (int mt = 0; mt < 4; mt++)
#pragma unroll
        for (int nt = 0; nt < 4; nt++)
#pragma unroll
            for (int q = 0; q < 4; q++) acc[mt][nt][q] = 0.f;

    load_chunk(0, 0);

#pragma unroll 1
    for (int c = 0; c < NCHUNK; c++) {
        const int buf = c & 1;
        if (c < NCHUNK - 1) { load_chunk(c + 1, buf ^ 1); cp_wait<1>(); }
        else                { cp_wait<0>(); }
        __syncthreads();

        const uint32_t sA = tiles + buf * BUF_B;
        const uint32_t sB = sA + TILE_B;
#pragma unroll
        for (int ks = 0; ks < 4; ks++) {
            uint32_t a[4][4], b[2][4];
            const uint32_t ua = (uint32_t)(((ks * 2 + akh) ^ xorv) << 4);
            const uint32_t ub = (uint32_t)(((ks * 2 + bkh) ^ xorv) << 4);
#pragma unroll
            for (int mt = 0; mt < 4; mt++)
                ldmatrix_x4(a[mt], sA + (uint32_t)((arow + mt * 16) * 128) + ua);
#pragma unroll
            for (int p = 0; p < 2; p++)
                ldmatrix_x4(b[p], sB + (uint32_t)((brow + p * 16) * 128) + ub);
#pragma unroll
            for (int mt = 0; mt < 4; mt++)
#pragma unroll
                for (int nt = 0; nt < 4; nt++)
                    mma_bf16(acc[mt][nt], a[mt], b[nt >> 1][(nt & 1) * 2],
                             b[nt >> 1][(nt & 1) * 2 + 1]);
        }
        __syncthreads();   // protect buf before it is refilled next iteration
    }

    // epilogue: acc + cc -> g_dist
    const int g = l >> 2, tig = l & 3;
#pragma unroll
    for (int mt = 0; mt < 4; mt++) {
        int r0 = bm + warp_m * 64 + mt * 16 + g;
#pragma unroll
        for (int nt = 0; nt < 4; nt++) {
            int cl = warp_n * 32 + nt * 8 + tig * 2;
            float c0 = s_cc[cl], c1 = s_cc[cl + 1];
            float2 v0 = make_float2(acc[mt][nt][0] + c0, acc[mt][nt][1] + c1);
            float2 v1 = make_float2(acc[mt][nt][2] + c0, acc[mt][nt][3] + c1);
            *(float2*)(g_dist + (size_t)r0 * C_ + bn + cl)       = v0;
            *(float2*)(g_dist + (size_t)(r0 + 8) * C_ + bn + cl) = v1;
        }
    }
}

// ================= per-row LSE (label column handled exactly at the end) =====
__global__ void __launch_bounds__(256) k_rowreduce() {
    int b = blockIdx.x, tid = threadIdx.x;
    int lab = g_label[b];
    const float4* r4  = (const float4*)(g_dist + (size_t)b * C_);
    const float4* sl4 = (const float4*)g_slog;

    float m[4] = {-1e30f, -1e30f, -1e30f, -1e30f};
    float s[4] = {0.f, 0.f, 0.f, 0.f};
    for (int c4 = tid; c4 < C_ / 4; c4 += 256) {
        float4 dv = r4[c4], sv = sl4[c4];
        float xs[4] = {-0.5f * (sv.x + dv.x), -0.5f * (sv.y + dv.y),
                       -0.5f * (sv.z + dv.z), -0.5f * (sv.w + dv.w)};
        int cb = c4 * 4;
#pragma unroll
        for (int j = 0; j < 4; j++) {
            if (cb + j == lab) continue;
            float x = xs[j];
            if (x > m[j]) { s[j] = s[j] * __expf(m[j] - x) + 1.f; m[j] = x; }
            else          { s[j] += __expf(x - m[j]); }
        }
    }
    float M = fmaxf(fmaxf(m[0], m[1]), fmaxf(m[2], m[3]));
    float S = s[0] * __expf(m[0] - M) + s[1] * __expf(m[1] - M)
            + s[2] * __expf(m[2] - M) + s[3] * __expf(m[3] - M);

    __shared__ float shm[256], shs[256];
    shm[tid] = M; shs[tid] = S; __syncthreads();
    for (int off = 128; off > 0; off >>= 1) {
        if (tid < off) {
            float ma = shm[tid], sa = shs[tid];
            float mb = shm[tid + off], sb = shs[tid + off];
            float Mx = fmaxf(ma, mb);
            shm[tid] = Mx;
            shs[tid] = sa * __expf(ma - Mx) + sb * __expf(mb - Mx);
        }
        __syncthreads();
    }
    if (tid == 0) {
        float Mr = shm[0], Sr = shs[0];
        float dl = g_dist[(size_t)b * C_ + lab];
        float sl = g_slog[lab];
        float x1 = -0.5f * (sl + dl);
        float x2 = -0.5f * (sl + (1.f + ALPHA) * dl);
        float M1 = fmaxf(Mr, x1);
        g_lse1[b] = M1 + logf(Sr * __expf(Mr - M1) + __expf(x1 - M1));
        float M2 = fmaxf(Mr, x2);
        g_lse2[b] = M2 + logf(Sr * __expf(Mr - M2) + __expf(x2 - M2));
    }
}

// ================= final write: logits + margin_logits =================
__global__ void k_final(float* __restrict__ out) {
    size_t i4 = (size_t)blockIdx.x * blockDim.x + threadIdx.x;
    const size_t total4 = (size_t)B_ * C_ / 4;
    if (i4 >= total4) return;
    int b  = (int)(i4 / (C_ / 4));
    int c4 = (int)(i4 % (C_ / 4));
    int c  = c4 * 4;

    float4 dv = ((const float4*)g_dist)[i4];
    float4 sv = ((const float4*)g_slog)[c4];
    int lab = g_label[b];
    float l1 = g_lse1[b], l2 = g_lse2[b];

    float dd[4] = {dv.x, dv.y, dv.z, dv.w};
    float ss[4] = {sv.x, sv.y, sv.z, sv.w};
    float r1[4], r2[4];
#pragma unroll
    for (int j = 0; j < 4; j++) {
        float x = -0.5f * (ss[j] + dd[j]);
        r1[j] = x - l1;
        float x2 = (c + j == lab) ? -0.5f * (ss[j] + (1.f + ALPHA) * dd[j]) : x;
        r2[j] = x2 - l2;
    }
    ((float4*)out)[i4] = make_float4(r1[0], r1[1], r1[2], r1[3]);
    ((float4*)(out + (size_t)B_ * C_))[i4] = make_float4(r2[0], r2[1], r2[2], r2[3]);
}

// ================= scalars =================
__global__ void __launch_bounds__(256) k_scal1(const float* __restrict__ feat,
                                               const float* __restrict__ centers) {
    int tid = threadIdx.x, blk = blockIdx.x;
    float cd = 0.f, det = 0.f;
    for (int i = blk * 256 + tid; i < B_ * D_; i += 64 * 256) {
        int b = i >> 7, d = i & 127;
        int lab = g_label[b];
        float diff = feat[i] - centers[(size_t)lab * D_ + d];
        cd += diff * diff;
        if (d == 0) det += g_slog[lab];
    }
    __shared__ float s1[256], s2[256];
    s1[tid] = cd; s2[tid] = det; __syncthreads();
    for (int off = 128; off > 0; off >>= 1) {
        if (tid < off) { s1[tid] += s1[tid + off]; s2[tid] += s2[tid + off]; }
        __syncthreads();
    }
    if (tid == 0) { g_pcd[blk] = s1[0]; g_pdet[blk] = s2[0]; }
}

__global__ void k_scal2(float* __restrict__ out) {
    if (threadIdx.x == 0 && blockIdx.x == 0) {
        float cd = 0.f, det = 0.f;
        for (int i = 0; i < 64; i++) { cd += g_pcd[i]; det += g_pdet[i]; }
        float cdist = cd * 0.5f;
        float reg   = 0.5f * (det + 1e-8f);
        float like  = (cdist - reg) / (float)B_;
        size_t off = (size_t)2 * B_ * C_;
        out[off + 0] = like;
        out[off + 1] = cdist;
        out[off + 2] = reg;
    }
}

// ================= launch =================
extern "C" void kernel_launch(void* const* d_in, const int* in_sizes, int n_in,
                              void* d_out, int out_size) {
    const float* feat     = (const float*)d_in[0];
    const int*   lab      = (const int*)  d_in[1];
    const float* centers  = (const float*)d_in[2];
    const float* log_covs = (const float*)d_in[3];
    float* out = (float*)d_out;

    cudaFuncSetAttribute(k_gemm_mma, cudaFuncAttributeMaxDynamicSharedMemorySize,
                         2 * BUF_B);

    k_detect<<<1, 256>>>(lab);
    k_gather<<<16, 256>>>(lab);
    k_prepA<<<(B_ * D_ + 255) / 256, 256>>>(feat);
    k_prepB<<<C_, 128>>>(centers, log_covs);

    dim3 grid(C_ / 128, B_ / 128);   // 250 x 32
    k_gemm_mma<<<grid, 256, 2 * BUF_B>>>();

    k_rowreduce<<<B_, 256>>>();
    k_final<<<(int)(((size_t)B_ * C_ / 4 + 255) / 256), 256>>>(out);

    k_scal1<<<64, 256>>>(feat, centers);
    k_scal2<<<1, 32>>>(out);
}